// round 7
// baseline (speedup 1.0000x reference)
#include <cuda_runtime.h>
#include <cuda_fp16.h>
#include <math.h>
#include <stdint.h>

#define Nn   32
#define Cc   192
#define Tt   256
#define Vv   25
#define Ss   3
#define MID  64
#define TV   6400          /* T*V */
#define C3   576           /* 3*C */
#define KF   1600          /* MID*Vv flattened contraction for attention */

// Scratch (static device arrays; allocation-free per harness rules)
__device__ __half g_qk [(size_t)Nn * 2 * Ss * Tt * KF];  // Q,K [n][part][s][t][c*25+v]
__device__ __half g_v  [(size_t)Nn * Ss * KF * Tt];      // V transposed [n][s][j][t]
__device__ __half g_att16[(size_t)Nn * Ss * Tt * Tt];    // [ns][t][q]
__device__ __half g_ytr[(size_t)Nn * TV * Cc];           // y transposed [n][p][d]
__device__ __half g_w_in16[C3 * Cc];
__device__ __half g_w_ff16[Cc * Cc];

// ---------------------------------------------------------------------------
// helpers
// ---------------------------------------------------------------------------
__device__ __forceinline__ uint32_t f2tf32(float x) {
    uint32_t r;
    asm("cvt.rna.tf32.f32 %0, %1;" : "=r"(r) : "f"(x));
    return r;
}
__device__ __forceinline__ void mma_tf32(float* d, const uint32_t* a,
                                         uint32_t b0, uint32_t b1) {
    asm volatile(
        "mma.sync.aligned.m16n8k8.row.col.f32.tf32.tf32.f32 "
        "{%0,%1,%2,%3}, {%4,%5,%6,%7}, {%8,%9}, {%0,%1,%2,%3};"
        : "+f"(d[0]), "+f"(d[1]), "+f"(d[2]), "+f"(d[3])
        : "r"(a[0]), "r"(a[1]), "r"(a[2]), "r"(a[3]), "r"(b0), "r"(b1));
}
__device__ __forceinline__ void mma_f16(float* d, const uint32_t* a,
                                        uint32_t b0, uint32_t b1) {
    asm volatile(
        "mma.sync.aligned.m16n8k16.row.col.f32.f16.f16.f32 "
        "{%0,%1,%2,%3}, {%4,%5,%6,%7}, {%8,%9}, {%0,%1,%2,%3};"
        : "+f"(d[0]), "+f"(d[1]), "+f"(d[2]), "+f"(d[3])
        : "r"(a[0]), "r"(a[1]), "r"(a[2]), "r"(a[3]), "r"(b0), "r"(b1));
}
__device__ __forceinline__ uint32_t smem_u32(const void* p) {
    return (uint32_t)__cvta_generic_to_shared(p);
}
__device__ __forceinline__ void cp16(uint32_t dst, const void* src) {
    asm volatile("cp.async.cg.shared.global [%0], [%1], 16;"
                 :: "r"(dst), "l"(src));
}
#define CP_COMMIT() asm volatile("cp.async.commit_group;")
#define CP_WAIT1()  asm volatile("cp.async.wait_group 1;" ::: "memory")

// ---------------------------------------------------------------------------
// fp16 tile format: [row][16 halves] = 8 b32 per row (32B). 16B granule u of
// row r stored at granule (u ^ ((r>>2)&1)). Conflict-free for cp.async writes
// and fragment LDS.32 reads.
// fp16 chunk: A[m rows], B[n rows], warp tile 32m x 64n, BK=16, acc[2][8][4].
// ---------------------------------------------------------------------------
__device__ __forceinline__ void mma16_chunk(const uint32_t* __restrict__ As,
                                            const uint32_t* __restrict__ Bs,
                                            float acc[2][8][4],
                                            int m0, int n0, int g, int ltg) {
    const int xk = 4 * ((g >> 2) & 1);
    const int ka = ltg + xk;
    const int kb = ltg + (xk ^ 4);
    uint32_t a[2][4];
#pragma unroll
    for (int mt = 0; mt < 2; mt++) {
        const uint32_t* Ar = As + (m0 + mt * 16 + g) * 8;
        a[mt][0] = Ar[ka];       // row g,   k[2ltg..]
        a[mt][1] = Ar[64 + ka];  // row g+8
        a[mt][2] = Ar[kb];       // row g,   k+8
        a[mt][3] = Ar[64 + kb];  // row g+8, k+8
    }
#pragma unroll
    for (int nt = 0; nt < 8; nt++) {
        const uint32_t* Br = Bs + (n0 + nt * 8 + g) * 8;
        const uint32_t b0 = Br[ka];
        const uint32_t b1 = Br[kb];
        mma_f16(acc[0][nt], a[0], b0, b1);
        mma_f16(acc[1][nt], a[1], b0, b1);
    }
}

// dst b32 offset for staging granule au of row r (base = row-0 of tile)
__device__ __forceinline__ int sw_off(int r, int au) {
    return r * 8 + (au ^ ((r >> 2) & 1)) * 4;
}

// ---------------------------------------------------------------------------
// Kernel 0: convert weights to fp16 (tiny).
// ---------------------------------------------------------------------------
__global__ void k_wconv(const float* __restrict__ w_in,
                        const float* __restrict__ w_ff) {
    const int i = blockIdx.x * 256 + threadIdx.x;
    if (i < C3 * Cc) g_w_in16[i] = __float2half(w_in[i]);
    if (i < Cc * Cc) g_w_ff16[i] = __float2half(w_ff[i]);
}

// ---------------------------------------------------------------------------
// Kernel 1: QKV projection (TF32 core, unchanged from R5).
// Epilogue writes fp16: Q/K token-major, V transposed [j][t].
// ---------------------------------------------------------------------------
template <int SBN, bool CA, bool CB>
__device__ __forceinline__ void mma_AkBn(const float* __restrict__ As,
                                         const float* __restrict__ Bs,
                                         float acc[2][8][4],
                                         int m0, int n0, int g, int ltg) {
    const int xk = 4 * ((g >> 1) & 3);
#pragma unroll
    for (int k8 = 0; k8 < 16; k8 += 8) {
        const int ka = (k8 + ltg) ^ xk;
        const int kb = (k8 + ltg + 4) ^ xk;
        uint32_t a[2][4];
#pragma unroll
        for (int mt = 0; mt < 2; mt++) {
            const float* Ar = As + (m0 + mt * 16 + g) * 16;
            a[mt][0] = CA ? f2tf32(Ar[ka]) : __float_as_uint(Ar[ka]);
            a[mt][1] = CA ? f2tf32(Ar[128 + ka]) : __float_as_uint(Ar[128 + ka]);
            a[mt][2] = CA ? f2tf32(Ar[kb]) : __float_as_uint(Ar[kb]);
            a[mt][3] = CA ? f2tf32(Ar[128 + kb]) : __float_as_uint(Ar[128 + kb]);
        }
        const float* B0 = Bs + (k8 + ltg) * SBN + n0 + g;
        const float* B1 = Bs + (k8 + ltg + 4) * SBN + n0 + g;
#pragma unroll
        for (int nt = 0; nt < 8; nt++) {
            const uint32_t b0 = CB ? f2tf32(B0[nt * 8]) : __float_as_uint(B0[nt * 8]);
            const uint32_t b1 = CB ? f2tf32(B1[nt * 8]) : __float_as_uint(B1[nt * 8]);
            mma_tf32(acc[0][nt], a[0], b0, b1);
            mma_tf32(acc[1][nt], a[1], b0, b1);
        }
    }
}

__global__ __launch_bounds__(256, 2) void k_qkv(const float* __restrict__ x,
                                                const float* __restrict__ w_in,
                                                const float* __restrict__ b_in) {
    __shared__ __align__(16) float As[2][64 * 16];
    __shared__ __align__(16) float Bs[2][16 * 264];
    const int n  = blockIdx.z;
    const int d0 = blockIdx.y * 64;
    const int p0 = blockIdx.x * 256;
    const int tid = threadIdx.x, warp = tid >> 5, lane = tid & 31;
    const int wm = warp >> 2, wn = warp & 3;
    const int g = lane >> 2, ltg = lane & 3;

    const float* xn = x + (size_t)n * Cc * TV;

    const int ar = tid >> 2, au = tid & 3;
    const int axc = 4 * (au ^ ((ar >> 1) & 3));
    const int br = tid >> 4, bc4 = (tid & 15) * 4;

    auto stage = [&](int buf, int k0) {
        cp16(smem_u32(&As[buf][ar * 16 + axc]),
             &w_in[(size_t)(d0 + ar) * Cc + k0 + au * 4]);
        const float* src = &xn[(size_t)(k0 + br) * TV + p0 + bc4];
        float* dst = &Bs[buf][br * 264 + bc4];
#pragma unroll
        for (int u = 0; u < 4; u++)
            cp16(smem_u32(dst + u * 64), src + u * 64);
    };

    float acc[2][8][4] = {};
    stage(0, 0);
    CP_COMMIT();
    const int NC = Cc / 16;
#pragma unroll 1
    for (int c = 0; c < NC; c++) {
        if (c + 1 < NC) stage((c + 1) & 1, (c + 1) * 16);
        CP_COMMIT();
        CP_WAIT1();
        __syncthreads();
        mma_AkBn<264, true, true>(As[c & 1], Bs[c & 1], acc,
                                  wm * 32, wn * 64, g, ltg);
        __syncthreads();
    }

    const int part = d0 / Cc;           // 0=Q,1=K,2=V
    const int s = (d0 % Cc) / MID;
#pragma unroll
    for (int mt = 0; mt < 2; mt++)
#pragma unroll
        for (int half = 0; half < 2; half++) {
            const int cch = wm * 32 + mt * 16 + g + half * 8;   // 0..63
            const float bias = b_in[d0 + cch];
#pragma unroll
            for (int nt = 0; nt < 8; nt++)
#pragma unroll
                for (int e = 0; e < 2; e++) {
                    const int p = p0 + wn * 64 + nt * 8 + ltg * 2 + e;
                    const int t = p / 25, v = p - t * 25;
                    const __half hv =
                        __float2half(acc[mt][nt][half * 2 + e] + bias);
                    if (part < 2) {
                        __half* qk = g_qk +
                            (((size_t)(n * 2 + part) * Ss + s) * Tt) * KF;
                        qk[(size_t)t * KF + cch * 25 + v] = hv;
                    } else {
                        __half* vb = g_v + ((size_t)(n * Ss + s) * KF) * Tt;
                        vb[(size_t)(cch * 25 + v) * Tt + t] = hv;
                    }
                }
        }
}

// ---------------------------------------------------------------------------
// Kernel 2: att = tanh(Q K^T / 1600). fp16 MMA. Block 64(t) x 256(q), K=1600.
// ---------------------------------------------------------------------------
__global__ __launch_bounds__(256, 2) void k_att() {
    __shared__ __align__(16) uint32_t As[2][64 * 8];     // Q tile
    __shared__ __align__(16) uint32_t Bs[2][256 * 8];    // K tile
    const int ns = blockIdx.z;
    const int n = ns / 3, s = ns - 3 * n;
    const int t0 = blockIdx.y * 64;
    const int tid = threadIdx.x, warp = tid >> 5, lane = tid & 31;
    const int wm = warp >> 2, wn = warp & 3;
    const int g = lane >> 2, ltg = lane & 3;

    const __half* Qb = g_qk + (((size_t)(n * 2 + 0) * Ss + s) * Tt) * KF;
    const __half* Kb = g_qk + (((size_t)(n * 2 + 1) * Ss + s) * Tt) * KF;

    const int r2 = tid >> 1, au = tid & 1;

    auto stage = [&](int buf, int k0) {
        if (tid < 128)
            cp16(smem_u32(&As[buf][sw_off(r2, au)]),
                 Qb + (size_t)(t0 + r2) * KF + k0 + au * 8);
#pragma unroll
        for (int i = 0; i < 2; i++) {
            const int q = r2 + 128 * i;
            cp16(smem_u32(&Bs[buf][sw_off(q, au)]),
                 Kb + (size_t)q * KF + k0 + au * 8);
        }
    };

    float acc[2][8][4] = {};
    stage(0, 0);
    CP_COMMIT();
    const int NC = KF / 16;
#pragma unroll 1
    for (int c = 0; c < NC; c++) {
        if (c + 1 < NC) stage((c + 1) & 1, (c + 1) * 16);
        CP_COMMIT();
        CP_WAIT1();
        __syncthreads();
        mma16_chunk(As[c & 1], Bs[c & 1], acc, wm * 32, wn * 64, g, ltg);
        __syncthreads();
    }

    const float scale = 1.0f / (float)KF;
    __half* arow = g_att16 + (size_t)ns * Tt * Tt;
#pragma unroll
    for (int mt = 0; mt < 2; mt++)
#pragma unroll
        for (int half = 0; half < 2; half++) {
            const int t = t0 + wm * 32 + mt * 16 + g + half * 8;
#pragma unroll
            for (int nt = 0; nt < 8; nt++) {
                const int q = wn * 64 + nt * 8 + ltg * 2;
                __half2 o = __floats2half2_rn(
                    tanhf(acc[mt][nt][half * 2 + 0] * scale),
                    tanhf(acc[mt][nt][half * 2 + 1] * scale));
                *(__half2*)&arow[(size_t)t * Tt + q] = o;
            }
        }
}

// ---------------------------------------------------------------------------
// Kernel 3: y = att @ V. fp16 MMA. Block 256(t, 8 warps) x 64(j), K=256.
// Output transposed: y_tr[p][d].
// ---------------------------------------------------------------------------
__global__ __launch_bounds__(256, 2) void k_y() {
    __shared__ __align__(16) uint32_t As[2][256 * 8];    // att tile
    __shared__ __align__(16) uint32_t Bs[2][64 * 8];     // V tile
    const int ns = blockIdx.z;
    const int n = ns / 3, s = ns - 3 * n;
    const int j0 = blockIdx.x * 64;
    const int tid = threadIdx.x, warp = tid >> 5, lane = tid & 31;
    const int g = lane >> 2, ltg = lane & 3;

    const __half* att = g_att16 + (size_t)ns * Tt * Tt;
    const __half* Vb  = g_v + ((size_t)(n * Ss + s) * KF) * Tt;

    const int r2 = tid >> 1, au = tid & 1;

    auto stage = [&](int buf, int k0) {
#pragma unroll
        for (int i = 0; i < 2; i++) {
            const int t = r2 + 128 * i;
            cp16(smem_u32(&As[buf][sw_off(t, au)]),
                 att + (size_t)t * Tt + k0 + au * 8);
        }
        if (tid < 128)
            cp16(smem_u32(&Bs[buf][sw_off(r2, au)]),
                 Vb + (size_t)(j0 + r2) * Tt + k0 + au * 8);
    };

    float acc[2][8][4] = {};
    stage(0, 0);
    CP_COMMIT();
    const int NC = Tt / 16;
#pragma unroll 1
    for (int c = 0; c < NC; c++) {
        if (c + 1 < NC) stage((c + 1) & 1, (c + 1) * 16);
        CP_COMMIT();
        CP_WAIT1();
        __syncthreads();
        mma16_chunk(As[c & 1], Bs[c & 1], acc, warp * 32, 0, g, ltg);
        __syncthreads();
    }

    __half* ytr = g_ytr + (size_t)n * TV * Cc;
#pragma unroll
    for (int mt = 0; mt < 2; mt++)
#pragma unroll
        for (int half = 0; half < 2; half++) {
            const int t = warp * 32 + mt * 16 + g + half * 8;
#pragma unroll
            for (int nt = 0; nt < 8; nt++)
#pragma unroll
                for (int e = 0; e < 2; e++) {
                    const int j = j0 + nt * 8 + ltg * 2 + e;
                    const int cch = j / 25, v = j - cch * 25;
                    ytr[(size_t)(t * 25 + v) * Cc + s * MID + cch] =
                        __float2half(acc[mt][nt][half * 2 + e]);
                }
        }
}

// ---------------------------------------------------------------------------
// Kernel 4: FF + BN + residual + LeakyReLU. fp16 MMA.
// Block 64(d) x 256(p), K=192. A = w_ff16[d][c], B = y_tr[p][c] rows.
// ---------------------------------------------------------------------------
__global__ __launch_bounds__(256, 2) void k_ff(const float* __restrict__ x,
                                               const float* __restrict__ b_ff,
                                               const float* __restrict__ gamma,
                                               const float* __restrict__ beta,
                                               const float* __restrict__ mean,
                                               const float* __restrict__ var,
                                               float* __restrict__ out) {
    __shared__ __align__(16) uint32_t As[2][64 * 8];     // w tile
    __shared__ __align__(16) uint32_t Bs[2][256 * 8];    // y tile
    const int n  = blockIdx.z;
    const int d0 = blockIdx.y * 64;
    const int p0 = blockIdx.x * 256;
    const int tid = threadIdx.x, warp = tid >> 5, lane = tid & 31;
    const int wm = warp >> 2, wn = warp & 3;
    const int g = lane >> 2, ltg = lane & 3;

    const __half* ytr = g_ytr + (size_t)n * TV * Cc;

    const int r2 = tid >> 1, au = tid & 1;

    auto stage = [&](int buf, int k0) {
        if (tid < 128)
            cp16(smem_u32(&As[buf][sw_off(r2, au)]),
                 g_w_ff16 + (size_t)(d0 + r2) * Cc + k0 + au * 8);
#pragma unroll
        for (int i = 0; i < 2; i++) {
            const int p = r2 + 128 * i;
            cp16(smem_u32(&Bs[buf][sw_off(p, au)]),
                 ytr + (size_t)(p0 + p) * Cc + k0 + au * 8);
        }
    };

    float acc[2][8][4] = {};
    stage(0, 0);
    CP_COMMIT();
    const int NC = Cc / 16;
#pragma unroll 1
    for (int c = 0; c < NC; c++) {
        if (c + 1 < NC) stage((c + 1) & 1, (c + 1) * 16);
        CP_COMMIT();
        CP_WAIT1();
        __syncthreads();
        mma16_chunk(As[c & 1], Bs[c & 1], acc, wm * 32, wn * 64, g, ltg);
        __syncthreads();
    }

    const float* xn = x + (size_t)n * Cc * TV;
    float* on = out + (size_t)n * Cc * TV;
#pragma unroll
    for (int mt = 0; mt < 2; mt++)
#pragma unroll
        for (int half = 0; half < 2; half++) {
            const int d = d0 + wm * 32 + mt * 16 + g + half * 8;
            const float inv = gamma[d] * rsqrtf(var[d] + 1e-5f);
            const float add = (b_ff[d] - mean[d]) * inv + beta[d];
#pragma unroll
            for (int nt = 0; nt < 8; nt++) {
                const int p = p0 + wn * 64 + nt * 8 + ltg * 2;
                const size_t off = (size_t)d * TV + p;
                float2 xv = *(const float2*)&xn[off];
                float z0 = xv.x + acc[mt][nt][half * 2 + 0] * inv + add;
                float z1 = xv.y + acc[mt][nt][half * 2 + 1] * inv + add;
                float2 o;
                o.x = z0 >= 0.f ? z0 : 0.1f * z0;
                o.y = z1 >= 0.f ? z1 : 0.1f * z1;
                *(float2*)&on[off] = o;
            }
        }
}

// ---------------------------------------------------------------------------
extern "C" void kernel_launch(void* const* d_in, const int* in_sizes, int n_in,
                              void* d_out, int out_size) {
    (void)in_sizes; (void)n_in; (void)out_size;
    const float* x     = (const float*)d_in[0];
    const float* w_in  = (const float*)d_in[1];
    const float* b_in  = (const float*)d_in[2];
    const float* w_ff  = (const float*)d_in[3];
    const float* b_ff  = (const float*)d_in[4];
    const float* gamma = (const float*)d_in[5];
    const float* beta  = (const float*)d_in[6];
    const float* mean  = (const float*)d_in[7];
    const float* var   = (const float*)d_in[8];
    float* out = (float*)d_out;

    k_wconv<<<(C3 * Cc + 255) / 256, 256>>>(w_in, w_ff);
    k_qkv<<<dim3(TV / 256, C3 / 64, Nn), 256>>>(x, w_in, b_in);
    k_att<<<dim3(1, Tt / 64, Nn * Ss), 256>>>();
    k_y  <<<dim3(KF / 64, 1, Nn * Ss), 256>>>();
    k_ff <<<dim3(TV / 256, Cc / 64, Nn), 256>>>(x, b_ff, gamma, beta,
                                                mean, var, out);
}

// round 8
// speedup vs baseline: 1.5061x; 1.5061x over previous
#include <cuda_runtime.h>
#include <cuda_fp16.h>
#include <math.h>
#include <stdint.h>

#define Nn   32
#define Cc   192
#define Tt   256
#define Vv   25
#define Ss   3
#define MID  64
#define TV   6400          /* T*V */
#define C3   576           /* 3*C */
#define KF   1600          /* MID*Vv flattened contraction for attention */

// Scratch (static device arrays; allocation-free per harness rules)
__device__ __half g_qk[(size_t)Nn * 2 * Ss * Tt * KF];   // Q,K fp16 [n][part][s][t][c*25+v]
__device__ float  g_tokV[(size_t)Nn * Ss * Tt * KF];     // V fp32 token-major [n][s][t][j]
__device__ float  g_att[(size_t)Nn * Ss * Tt * Tt];      // [ns][t][q] (tf32-rounded)
__device__ float  g_y[(size_t)Nn * Cc * TV];             // [n][d][t*25+v] (tf32-rounded)

// ---------------------------------------------------------------------------
// helpers
// ---------------------------------------------------------------------------
__device__ __forceinline__ uint32_t f2tf32(float x) {
    uint32_t r;
    asm("cvt.rna.tf32.f32 %0, %1;" : "=r"(r) : "f"(x));
    return r;
}
__device__ __forceinline__ float rnd_tf32(float x) {
    return __uint_as_float(f2tf32(x));
}
__device__ __forceinline__ void mma_tf32(float* d, const uint32_t* a,
                                         uint32_t b0, uint32_t b1) {
    asm volatile(
        "mma.sync.aligned.m16n8k8.row.col.f32.tf32.tf32.f32 "
        "{%0,%1,%2,%3}, {%4,%5,%6,%7}, {%8,%9}, {%0,%1,%2,%3};"
        : "+f"(d[0]), "+f"(d[1]), "+f"(d[2]), "+f"(d[3])
        : "r"(a[0]), "r"(a[1]), "r"(a[2]), "r"(a[3]), "r"(b0), "r"(b1));
}
__device__ __forceinline__ void mma_f16(float* d, const uint32_t* a,
                                        uint32_t b0, uint32_t b1) {
    asm volatile(
        "mma.sync.aligned.m16n8k16.row.col.f32.f16.f16.f32 "
        "{%0,%1,%2,%3}, {%4,%5,%6,%7}, {%8,%9}, {%0,%1,%2,%3};"
        : "+f"(d[0]), "+f"(d[1]), "+f"(d[2]), "+f"(d[3])
        : "r"(a[0]), "r"(a[1]), "r"(a[2]), "r"(a[3]), "r"(b0), "r"(b1));
}
__device__ __forceinline__ uint32_t smem_u32(const void* p) {
    return (uint32_t)__cvta_generic_to_shared(p);
}
__device__ __forceinline__ void cp16(uint32_t dst, const void* src) {
    asm volatile("cp.async.cg.shared.global [%0], [%1], 16;"
                 :: "r"(dst), "l"(src));
}
#define CP_COMMIT() asm volatile("cp.async.commit_group;")
#define CP_WAIT1()  asm volatile("cp.async.wait_group 1;" ::: "memory")

// ---------------------------------------------------------------------------
// TF32 fragment math (identical to R6).
// A tiles: [m][k] XOR-16: element (m,k) at m*16 + (k ^ 4*((m>>1)&3))
// B [k][n] tiles: row stride SBN, plain.  Warp tile 32m x 64n, acc[2][8][4].
// ---------------------------------------------------------------------------
template <int SBN, bool CA, bool CB>
__device__ __forceinline__ void mma_AkBn(const float* __restrict__ As,
                                         const float* __restrict__ Bs,
                                         float acc[2][8][4],
                                         int m0, int n0, int g, int ltg) {
    const int xk = 4 * ((g >> 1) & 3);
#pragma unroll
    for (int k8 = 0; k8 < 16; k8 += 8) {
        const int ka = (k8 + ltg) ^ xk;
        const int kb = (k8 + ltg + 4) ^ xk;
        uint32_t a[2][4];
#pragma unroll
        for (int mt = 0; mt < 2; mt++) {
            const float* Ar = As + (m0 + mt * 16 + g) * 16;
            a[mt][0] = CA ? f2tf32(Ar[ka]) : __float_as_uint(Ar[ka]);
            a[mt][1] = CA ? f2tf32(Ar[128 + ka]) : __float_as_uint(Ar[128 + ka]);
            a[mt][2] = CA ? f2tf32(Ar[kb]) : __float_as_uint(Ar[kb]);
            a[mt][3] = CA ? f2tf32(Ar[128 + kb]) : __float_as_uint(Ar[128 + kb]);
        }
        const float* B0 = Bs + (k8 + ltg) * SBN + n0 + g;
        const float* B1 = Bs + (k8 + ltg + 4) * SBN + n0 + g;
#pragma unroll
        for (int nt = 0; nt < 8; nt++) {
            const uint32_t b0 = CB ? f2tf32(B0[nt * 8]) : __float_as_uint(B0[nt * 8]);
            const uint32_t b1 = CB ? f2tf32(B1[nt * 8]) : __float_as_uint(B1[nt * 8]);
            mma_tf32(acc[0][nt], a[0], b0, b1);
            mma_tf32(acc[1][nt], a[1], b0, b1);
        }
    }
}

// ---------------------------------------------------------------------------
// fp16 fragment math (R7's proven k_att core).
// Tile format: [row][16 halves] = 8 b32/row; 16B granule u of row r stored at
// granule (u ^ ((r>>2)&1)).
// ---------------------------------------------------------------------------
__device__ __forceinline__ void mma16_chunk(const uint32_t* __restrict__ As,
                                            const uint32_t* __restrict__ Bs,
                                            float acc[2][8][4],
                                            int m0, int n0, int g, int ltg) {
    const int xk = 4 * ((g >> 2) & 1);
    const int ka = ltg + xk;
    const int kb = ltg + (xk ^ 4);
    uint32_t a[2][4];
#pragma unroll
    for (int mt = 0; mt < 2; mt++) {
        const uint32_t* Ar = As + (m0 + mt * 16 + g) * 8;
        a[mt][0] = Ar[ka];
        a[mt][1] = Ar[64 + ka];
        a[mt][2] = Ar[kb];
        a[mt][3] = Ar[64 + kb];
    }
#pragma unroll
    for (int nt = 0; nt < 8; nt++) {
        const uint32_t* Br = Bs + (n0 + nt * 8 + g) * 8;
        const uint32_t b0 = Br[ka];
        const uint32_t b1 = Br[kb];
        mma_f16(acc[0][nt], a[0], b0, b1);
        mma_f16(acc[1][nt], a[1], b0, b1);
    }
}
__device__ __forceinline__ int sw_off(int r, int au) {
    return r * 8 + (au ^ ((r >> 2) & 1)) * 4;
}

// ---------------------------------------------------------------------------
// Kernel 1: QKV projection (TF32 core). Grid: x = d-tile (9) so the 9 blocks
// sharing one x-slice are launch-adjacent -> slice served from L2.
// Epilogue: Q,K -> fp16 token-major; V -> fp32 token-major (tf32-rounded).
// ---------------------------------------------------------------------------
__global__ __launch_bounds__(256, 2) void k_qkv(const float* __restrict__ x,
                                                const float* __restrict__ w_in,
                                                const float* __restrict__ b_in) {
    __shared__ __align__(16) float As[2][64 * 16];
    __shared__ __align__(16) float Bs[2][16 * 264];
    const int n  = blockIdx.z;
    const int d0 = blockIdx.x * 64;
    const int p0 = blockIdx.y * 256;
    const int tid = threadIdx.x, warp = tid >> 5, lane = tid & 31;
    const int wm = warp >> 2, wn = warp & 3;
    const int g = lane >> 2, ltg = lane & 3;

    const float* xn = x + (size_t)n * Cc * TV;

    const int ar = tid >> 2, au = tid & 3;
    const int axc = 4 * (au ^ ((ar >> 1) & 3));
    const int br = tid >> 4, bc4 = (tid & 15) * 4;

    auto stage = [&](int buf, int k0) {
        cp16(smem_u32(&As[buf][ar * 16 + axc]),
             &w_in[(size_t)(d0 + ar) * Cc + k0 + au * 4]);
        const float* src = &xn[(size_t)(k0 + br) * TV + p0 + bc4];
        float* dst = &Bs[buf][br * 264 + bc4];
#pragma unroll
        for (int u = 0; u < 4; u++)
            cp16(smem_u32(dst + u * 64), src + u * 64);
    };

    float acc[2][8][4] = {};
    stage(0, 0);
    CP_COMMIT();
    const int NC = Cc / 16;
#pragma unroll 1
    for (int c = 0; c < NC; c++) {
        if (c + 1 < NC) stage((c + 1) & 1, (c + 1) * 16);
        CP_COMMIT();
        CP_WAIT1();
        __syncthreads();
        mma_AkBn<264, true, true>(As[c & 1], Bs[c & 1], acc,
                                  wm * 32, wn * 64, g, ltg);
        __syncthreads();
    }

    const int part = d0 / Cc;           // 0=Q,1=K,2=V
    const int s = (d0 % Cc) / MID;
    if (part < 2) {
        __half* qk = g_qk + (((size_t)(n * 2 + part) * Ss + s) * Tt) * KF;
#pragma unroll
        for (int mt = 0; mt < 2; mt++)
#pragma unroll
            for (int half = 0; half < 2; half++) {
                const int cch = wm * 32 + mt * 16 + g + half * 8;
                const float bias = b_in[d0 + cch];
#pragma unroll
                for (int nt = 0; nt < 8; nt++)
#pragma unroll
                    for (int e = 0; e < 2; e++) {
                        const int p = p0 + wn * 64 + nt * 8 + ltg * 2 + e;
                        const int t = p / 25, v = p - t * 25;
                        qk[(size_t)t * KF + cch * 25 + v] =
                            __float2half(acc[mt][nt][half * 2 + e] + bias);
                    }
            }
    } else {
        float* vb = g_tokV + (((size_t)(n * Ss + s)) * Tt) * KF;
#pragma unroll
        for (int mt = 0; mt < 2; mt++)
#pragma unroll
            for (int half = 0; half < 2; half++) {
                const int cch = wm * 32 + mt * 16 + g + half * 8;
                const float bias = b_in[d0 + cch];
#pragma unroll
                for (int nt = 0; nt < 8; nt++)
#pragma unroll
                    for (int e = 0; e < 2; e++) {
                        const int p = p0 + wn * 64 + nt * 8 + ltg * 2 + e;
                        const int t = p / 25, v = p - t * 25;
                        vb[(size_t)t * KF + cch * 25 + v] =
                            rnd_tf32(acc[mt][nt][half * 2 + e] + bias);
                    }
            }
    }
}

// ---------------------------------------------------------------------------
// Kernel 2: att = tanh(Q K^T / 1600). fp16 MMA (R7 core), fp32 output.
// Block 64(t) x 256(q), K=1600.
// ---------------------------------------------------------------------------
__global__ __launch_bounds__(256, 2) void k_att() {
    __shared__ __align__(16) uint32_t As[2][64 * 8];
    __shared__ __align__(16) uint32_t Bs[2][256 * 8];
    const int ns = blockIdx.z;
    const int n = ns / 3, s = ns - 3 * n;
    const int t0 = blockIdx.y * 64;
    const int tid = threadIdx.x, warp = tid >> 5, lane = tid & 31;
    const int wm = warp >> 2, wn = warp & 3;
    const int g = lane >> 2, ltg = lane & 3;

    const __half* Qb = g_qk + (((size_t)(n * 2 + 0) * Ss + s) * Tt) * KF;
    const __half* Kb = g_qk + (((size_t)(n * 2 + 1) * Ss + s) * Tt) * KF;

    const int r2 = tid >> 1, au = tid & 1;

    auto stage = [&](int buf, int k0) {
        if (tid < 128)
            cp16(smem_u32(&As[buf][sw_off(r2, au)]),
                 Qb + (size_t)(t0 + r2) * KF + k0 + au * 8);
#pragma unroll
        for (int i = 0; i < 2; i++) {
            const int q = r2 + 128 * i;
            cp16(smem_u32(&Bs[buf][sw_off(q, au)]),
                 Kb + (size_t)q * KF + k0 + au * 8);
        }
    };

    float acc[2][8][4] = {};
    stage(0, 0);
    CP_COMMIT();
    const int NC = KF / 16;
#pragma unroll 1
    for (int c = 0; c < NC; c++) {
        if (c + 1 < NC) stage((c + 1) & 1, (c + 1) * 16);
        CP_COMMIT();
        CP_WAIT1();
        __syncthreads();
        mma16_chunk(As[c & 1], Bs[c & 1], acc, wm * 32, wn * 64, g, ltg);
        __syncthreads();
    }

    const float scale = 1.0f / (float)KF;
    float* arow = g_att + (size_t)ns * Tt * Tt;
#pragma unroll
    for (int mt = 0; mt < 2; mt++)
#pragma unroll
        for (int half = 0; half < 2; half++) {
            const int t = t0 + wm * 32 + mt * 16 + g + half * 8;
#pragma unroll
            for (int nt = 0; nt < 8; nt++) {
                const int q = wn * 64 + nt * 8 + ltg * 2;
                float2 o;
                o.x = rnd_tf32(tanhf(acc[mt][nt][half * 2 + 0] * scale));
                o.y = rnd_tf32(tanhf(acc[mt][nt][half * 2 + 1] * scale));
                *(float2*)&arow[(size_t)t * Tt + q] = o;
            }
        }
}

// ---------------------------------------------------------------------------
// Kernel 3: y = att @ V_t (TF32, identical to R6). Block 256(t) x 64(j), K=256.
// ---------------------------------------------------------------------------
__global__ __launch_bounds__(256, 2) void k_y() {
    __shared__ __align__(16) float As[2][256 * 16];
    __shared__ __align__(16) float Bs[2][16 * 72];
    const int ns = blockIdx.z;
    const int n = ns / 3, s = ns - 3 * n;
    const int j0 = blockIdx.x * 64;
    const int tid = threadIdx.x, warp = tid >> 5, lane = tid & 31;
    const int g = lane >> 2, ltg = lane & 3;

    const float* att = g_att + (size_t)ns * Tt * Tt;
    const float* Vb  = g_tokV + (((size_t)(n * Ss + s)) * Tt) * KF;

    const int ar = tid >> 2, au = tid & 3;
    const int axc = 4 * (au ^ ((ar >> 1) & 3));
    const int br = tid >> 4, bc4 = (tid & 15) * 4;

    auto stage = [&](int buf, int k0) {
#pragma unroll
        for (int i = 0; i < 4; i++) {
            const int t = ar + 64 * i;
            cp16(smem_u32(&As[buf][t * 16 + axc]),
                 &att[(size_t)t * Tt + k0 + au * 4]);
        }
        cp16(smem_u32(&Bs[buf][br * 72 + bc4]),
             &Vb[(size_t)(k0 + br) * KF + j0 + bc4]);
    };

    float acc[2][8][4] = {};
    stage(0, 0);
    CP_COMMIT();
    const int NC = Tt / 16;
#pragma unroll 1
    for (int c = 0; c < NC; c++) {
        if (c + 1 < NC) stage((c + 1) & 1, (c + 1) * 16);
        CP_COMMIT();
        CP_WAIT1();
        __syncthreads();
        mma_AkBn<72, false, false>(As[c & 1], Bs[c & 1], acc,
                                   warp * 32, 0, g, ltg);
        __syncthreads();
    }

    float* yb = g_y + (size_t)n * Cc * TV + (size_t)(s * MID) * TV;
#pragma unroll
    for (int mt = 0; mt < 2; mt++)
#pragma unroll
        for (int half = 0; half < 2; half++) {
            const int t = warp * 32 + mt * 16 + g + half * 8;
#pragma unroll
            for (int nt = 0; nt < 8; nt++)
#pragma unroll
                for (int e = 0; e < 2; e++) {
                    const int j = j0 + nt * 8 + ltg * 2 + e;
                    const int cch = j / 25, v = j - cch * 25;
                    yb[(size_t)cch * TV + t * 25 + v] =
                        rnd_tf32(acc[mt][nt][half * 2 + e]);
                }
        }
}

// ---------------------------------------------------------------------------
// Kernel 4: FF + BN + residual + LeakyReLU (TF32, R6). Grid: x = d-tile (3)
// so the 3 blocks sharing one y-slice are launch-adjacent.
// ---------------------------------------------------------------------------
__global__ __launch_bounds__(256, 2) void k_ff(const float* __restrict__ x,
                                               const float* __restrict__ w_ff,
                                               const float* __restrict__ b_ff,
                                               const float* __restrict__ gamma,
                                               const float* __restrict__ beta,
                                               const float* __restrict__ mean,
                                               const float* __restrict__ var,
                                               float* __restrict__ out) {
    __shared__ __align__(16) float As[2][64 * 16];
    __shared__ __align__(16) float Bs[2][16 * 264];
    const int n  = blockIdx.z;
    const int d0 = blockIdx.x * 64;
    const int p0 = blockIdx.y * 256;
    const int tid = threadIdx.x, warp = tid >> 5, lane = tid & 31;
    const int wm = warp >> 2, wn = warp & 3;
    const int g = lane >> 2, ltg = lane & 3;

    const float* yn = g_y + (size_t)n * Cc * TV;

    const int ar = tid >> 2, au = tid & 3;
    const int axc = 4 * (au ^ ((ar >> 1) & 3));
    const int br = tid >> 4, bc4 = (tid & 15) * 4;

    auto stage = [&](int buf, int k0) {
        cp16(smem_u32(&As[buf][ar * 16 + axc]),
             &w_ff[(size_t)(d0 + ar) * Cc + k0 + au * 4]);
        const float* src = &yn[(size_t)(k0 + br) * TV + p0 + bc4];
        float* dst = &Bs[buf][br * 264 + bc4];
#pragma unroll
        for (int u = 0; u < 4; u++)
            cp16(smem_u32(dst + u * 64), src + u * 64);
    };

    float acc[2][8][4] = {};
    stage(0, 0);
    CP_COMMIT();
    const int NC = Cc / 16;
#pragma unroll 1
    for (int c = 0; c < NC; c++) {
        if (c + 1 < NC) stage((c + 1) & 1, (c + 1) * 16);
        CP_COMMIT();
        CP_WAIT1();
        __syncthreads();
        mma_AkBn<264, true, false>(As[c & 1], Bs[c & 1], acc,
                                   wm * 32, wn * 64, g, ltg);
        __syncthreads();
    }

    const float* xn = x + (size_t)n * Cc * TV;
    float* on = out + (size_t)n * Cc * TV;
#pragma unroll
    for (int mt = 0; mt < 2; mt++)
#pragma unroll
        for (int half = 0; half < 2; half++) {
            const int d = d0 + wm * 32 + mt * 16 + g + half * 8;
            const float inv = gamma[d] * rsqrtf(var[d] + 1e-5f);
            const float add = (b_ff[d] - mean[d]) * inv + beta[d];
#pragma unroll
            for (int nt = 0; nt < 8; nt++) {
                const int p = p0 + wn * 64 + nt * 8 + ltg * 2;
                const size_t off = (size_t)d * TV + p;
                float2 xv = *(const float2*)&xn[off];
                float z0 = xv.x + acc[mt][nt][half * 2 + 0] * inv + add;
                float z1 = xv.y + acc[mt][nt][half * 2 + 1] * inv + add;
                float2 o;
                o.x = z0 >= 0.f ? z0 : 0.1f * z0;
                o.y = z1 >= 0.f ? z1 : 0.1f * z1;
                *(float2*)&on[off] = o;
            }
        }
}

// ---------------------------------------------------------------------------
extern "C" void kernel_launch(void* const* d_in, const int* in_sizes, int n_in,
                              void* d_out, int out_size) {
    (void)in_sizes; (void)n_in; (void)out_size;
    const float* x     = (const float*)d_in[0];
    const float* w_in  = (const float*)d_in[1];
    const float* b_in  = (const float*)d_in[2];
    const float* w_ff  = (const float*)d_in[3];
    const float* b_ff  = (const float*)d_in[4];
    const float* gamma = (const float*)d_in[5];
    const float* beta  = (const float*)d_in[6];
    const float* mean  = (const float*)d_in[7];
    const float* var   = (const float*)d_in[8];
    float* out = (float*)d_out;

    k_qkv<<<dim3(C3 / 64, TV / 256, Nn), 256>>>(x, w_in, b_in);
    k_att<<<dim3(1, Tt / 64, Nn * Ss), 256>>>();
    k_y  <<<dim3(KF / 64, 1, Nn * Ss), 256>>>();
    k_ff <<<dim3(Cc / 64, TV / 256, Nn), 256>>>(x, w_ff, b_ff, gamma, beta,
                                                mean, var, out);
}